// round 2
// baseline (speedup 1.0000x reference)
#include <cuda_runtime.h>

// Problem constants (fixed by the reference)
#define NB   50000
#define DIM  51
#define DD   2601          // 51*51
#define BATCH 8192

// Partial-sum slots (deterministic two-phase reduction, no atomics)
#define CHAIN_BLOCKS  BATCH                    // 8192, 1 block per sample
#define BMV_WPB       8                        // warps per block
#define BMV_WARPS     (4 * BATCH)              // 4 loss modes x 8192
#define BMV_BLOCKS    (BMV_WARPS / BMV_WPB)    // 4096
#define SMALL_TPB     256
#define SMALL_BLOCKS  (BATCH / SMALL_TPB)      // 32

#define PART_CHAIN 0
#define PART_BMV   (PART_CHAIN + CHAIN_BLOCKS)
#define PART_SMALL (PART_BMV + BMV_BLOCKS)
#define PART_TOTAL (PART_SMALL + SMALL_BLOCKS) // 12320

__device__ float g_part[PART_TOTAL];

// ---------------------------------------------------------------------------
// Chain loss: per sample, CD = C(51x51) @ D(51x51), mean|E - CD|.
// Block = 64 threads (thread j owns output column j, j<51).
// C staged in SMEM (broadcast reads), D column held in 51 registers,
// E streamed coalesced from global. 4 accumulators for FFMA ILP.
// ---------------------------------------------------------------------------
__global__ void __launch_bounds__(64) chain_kernel(
    const int* __restrict__ nfc, const float* __restrict__ rel)
{
    const int s  = blockIdx.x;
    const int i0 = nfc[3 * s];
    const int i1 = nfc[3 * s + 1];
    const int i2 = nfc[3 * s + 2];
    const float* __restrict__ C  = rel + (long)i0 * DD;
    const float* __restrict__ Dm = rel + (long)i1 * DD;
    const float* __restrict__ E  = rel + (long)i2 * DD;

    __shared__ float Cs[DD];
    const int tid = threadIdx.x;
    for (int t = tid; t < DD; t += 64) Cs[t] = C[t];

    float dreg[DIM];
    const int j = tid;
    if (j < DIM) {
        #pragma unroll
        for (int k = 0; k < DIM; k++) dreg[k] = Dm[k * DIM + j];
    } else {
        #pragma unroll
        for (int k = 0; k < DIM; k++) dreg[k] = 0.f;
    }
    __syncthreads();

    float local = 0.f;
    if (j < DIM) {
        #pragma unroll 1
        for (int i = 0; i < DIM; i++) {
            const float* __restrict__ crow = Cs + i * DIM;
            float a0 = 0.f, a1 = 0.f, a2 = 0.f, a3 = 0.f;
            #pragma unroll
            for (int k = 0; k < 48; k += 4) {
                a0 = fmaf(crow[k    ], dreg[k    ], a0);
                a1 = fmaf(crow[k + 1], dreg[k + 1], a1);
                a2 = fmaf(crow[k + 2], dreg[k + 2], a2);
                a3 = fmaf(crow[k + 3], dreg[k + 3], a3);
            }
            a0 = fmaf(crow[48], dreg[48], a0);
            a1 = fmaf(crow[49], dreg[49], a1);
            a2 = fmaf(crow[50], dreg[50], a2);
            float acc = (a0 + a1) + (a2 + a3);
            local += fabsf(E[i * DIM + j] - acc);
        }
    }

    // reduce over 2 warps
    #pragma unroll
    for (int o = 16; o; o >>= 1)
        local += __shfl_xor_sync(0xffffffffu, local, o);
    __shared__ float wsum[2];
    if ((tid & 31) == 0) wsum[tid >> 5] = local;
    __syncthreads();
    if (tid == 0)
        g_part[PART_CHAIN + s] = (wsum[0] + wsum[1]) * (1.0f / (float)DD);
}

// ---------------------------------------------------------------------------
// bmv losses (nf1, nf3, nf4, nf3_neg): warp per sample, mode = warp_id >> 13.
// Each warp: gather c,d (51-vec), one 51x51 matrix; coalesced row loads,
// butterfly-reduced dot products for cr/dr; euclidean + regs + mode formula.
// ---------------------------------------------------------------------------
__global__ void __launch_bounds__(BMV_WPB * 32) bmv_kernel(
    const int* __restrict__ nf1,  const int* __restrict__ nf3,
    const int* __restrict__ nf4,  const int* __restrict__ nf3n,
    const float* __restrict__ cls, const float* __restrict__ rel)
{
    const int wlocal = threadIdx.x >> 5;
    const int w    = blockIdx.x * BMV_WPB + wlocal;
    const int lane = threadIdx.x & 31;
    const int mode = w >> 13;
    const int s    = w & (BATCH - 1);

    const int* __restrict__ idx =
        (mode == 0) ? nf1 : (mode == 1) ? nf3 : (mode == 2) ? nf4 : nf3n;
    int ic, ir, id_;
    if (mode == 2) { ir = idx[3*s]; ic = idx[3*s+1]; id_ = idx[3*s+2]; }
    else           { ic = idx[3*s]; ir = idx[3*s+1]; id_ = idx[3*s+2]; }

    const float* __restrict__ cp = cls + (long)ic  * DIM;
    const float* __restrict__ dp = cls + (long)id_ * DIM;
    const bool hi = (lane < DIM - 32);            // lane < 19 owns element lane+32
    const float c0 = cp[lane];
    const float d0 = dp[lane];
    const float c1 = hi ? cp[lane + 32] : 0.f;
    const float d1 = hi ? dp[lane + 32] : 0.f;

    // regularizers over first 50 dims (element 50 = lane 18 hi slot, excluded)
    float sc = c0 * c0 + ((lane < 18) ? c1 * c1 : 0.f);
    float sd = d0 * d0 + ((lane < 18) ? d1 * d1 : 0.f);
    #pragma unroll
    for (int o = 16; o; o >>= 1) {
        sc += __shfl_xor_sync(0xffffffffu, sc, o);
        sd += __shfl_xor_sync(0xffffffffu, sd, o);
    }
    const float reg_c = fabsf(sqrtf(sc) - 1.0f);
    const float reg_d = fabsf(sqrtf(sd) - 1.0f);
    const float c_last = __shfl_sync(0xffffffffu, c1, 18);
    const float d_last = __shfl_sync(0xffffffffu, d1, 18);

    const float* __restrict__ rm = rel + (long)ir * DD;
    float euc2 = 0.f, cr50 = 0.f, dr50 = 0.f;
    #pragma unroll 1
    for (int i = 0; i < DIM; i++) {
        const float* __restrict__ row = rm + i * DIM;
        const float a0 = row[lane];
        const float a1 = hi ? row[lane + 32] : 0.f;
        float pc = a0 * c0 + a1 * c1;
        float pd = a0 * d0 + a1 * d1;
        #pragma unroll
        for (int o = 16; o; o >>= 1) {
            pc += __shfl_xor_sync(0xffffffffu, pc, o);
            pd += __shfl_xor_sync(0xffffffffu, pd, o);
        }
        if (i < DIM - 1) { float t = pd - pc; euc2 += t * t; }
        else             { cr50 = pc; dr50 = pd; }
    }
    const float euc = sqrtf(euc2);

    float core;
    if (mode == 0) {
        float rc = fmaxf(cr50, 0.f), rd = fmaxf(dr50, 0.f);
        core = fmaxf(euc + rc - rd, 0.f);
    } else {
        float rc = fmaxf(c_last, 0.f), rd = fmaxf(d_last, 0.f);
        if (mode == 1)      core = fmaxf(euc + rc - rd, 0.f);
        else if (mode == 2) core = fmaxf(euc - rc - rd, 0.f);
        else                core = rc + rd - euc;          // nf3_neg: -(euc-rc-rd)
    }
    const float loss = core + reg_c + reg_d;

    __shared__ float ws[BMV_WPB];
    if (lane == 0) ws[wlocal] = loss;
    __syncthreads();
    if (threadIdx.x == 0) {
        float t = 0.f;
        #pragma unroll
        for (int k = 0; k < BMV_WPB; k++) t += ws[k];
        g_part[PART_BMV + blockIdx.x] = t;
    }
}

// ---------------------------------------------------------------------------
// nf2 + top + (-radius): thread per sample.
// ---------------------------------------------------------------------------
__global__ void __launch_bounds__(SMALL_TPB) small_kernel(
    const int* __restrict__ nf2,   const int* __restrict__ top,
    const int* __restrict__ radius, const float* __restrict__ cls)
{
    const int s = blockIdx.x * SMALL_TPB + threadIdx.x;
    const float* __restrict__ c = cls + (long)nf2[3*s]     * DIM;
    const float* __restrict__ d = cls + (long)nf2[3*s + 1] * DIM;
    const float* __restrict__ e = cls + (long)nf2[3*s + 2] * DIM;

    float s12 = 0.f, s13 = 0.f, s23 = 0.f, n1 = 0.f, n2 = 0.f, n3 = 0.f;
    #pragma unroll 5
    for (int k = 0; k < DIM - 1; k++) {
        const float x1 = c[k], x2 = d[k], x3 = e[k];
        const float d12 = x2 - x1, d13 = x3 - x1, d23 = x3 - x2;
        s12 = fmaf(d12, d12, s12);
        s13 = fmaf(d13, d13, s13);
        s23 = fmaf(d23, d23, s23);
        n1  = fmaf(x1, x1, n1);
        n2  = fmaf(x2, x2, n2);
        n3  = fmaf(x3, x3, n3);
    }
    const float rc = fmaxf(c[DIM - 1], 0.f);
    const float rd = fmaxf(d[DIM - 1], 0.f);
    const float re = fmaxf(e[DIM - 1], 0.f);
    float loss2 = fmaxf(sqrtf(s12) - (rc + rd), 0.f)
                + fmaxf(sqrtf(s13) - rc, 0.f)
                + fmaxf(sqrtf(s23) - rd, 0.f)
                + fmaxf(fminf(rc, rd) - re, 0.f)
                + fabsf(sqrtf(n1) - 1.f)
                + fabsf(sqrtf(n2) - 1.f)
                + fabsf(sqrtf(n3) - 1.f);

    const float td = cls[(long)top[s] * DIM + (DIM - 1)];
    const float loss_top = fabsf(fmaxf(td, 0.f) - 5.0f);

    const float rr = cls[(long)radius[s] * DIM + (DIM - 1)];
    const float loss7 = fminf(0.f, rr);

    float v = loss2 + loss_top - loss7;

    // block reduce (256 threads)
    #pragma unroll
    for (int o = 16; o; o >>= 1)
        v += __shfl_xor_sync(0xffffffffu, v, o);
    __shared__ float ws[SMALL_TPB / 32];
    if ((threadIdx.x & 31) == 0) ws[threadIdx.x >> 5] = v;
    __syncthreads();
    if (threadIdx.x == 0) {
        float t = 0.f;
        #pragma unroll
        for (int k = 0; k < SMALL_TPB / 32; k++) t += ws[k];
        g_part[PART_SMALL + blockIdx.x] = t;
    }
}

// ---------------------------------------------------------------------------
// Final deterministic reduction -> out[0] = sum / B
// ---------------------------------------------------------------------------
__global__ void __launch_bounds__(1024) finish_kernel(float* __restrict__ out)
{
    float t = 0.f;
    for (int i = threadIdx.x; i < PART_TOTAL; i += 1024) t += g_part[i];
    #pragma unroll
    for (int o = 16; o; o >>= 1)
        t += __shfl_xor_sync(0xffffffffu, t, o);
    __shared__ float ws[32];
    if ((threadIdx.x & 31) == 0) ws[threadIdx.x >> 5] = t;
    __syncthreads();
    if (threadIdx.x < 32) {
        float v = ws[threadIdx.x];
        #pragma unroll
        for (int o = 16; o; o >>= 1)
            v += __shfl_xor_sync(0xffffffffu, v, o);
        if (threadIdx.x == 0) out[0] = v * (1.0f / (float)BATCH);
    }
}

// ---------------------------------------------------------------------------
// Inputs (metadata order):
//  0 nf1(B,3) 1 nf2(B,3) 2 nf3(B,3) 3 nf4(B,3) 4 top(B) 5 nf3_neg(B,3)
//  6 nf_inclusion(B,2) [unused] 7 nf_chain(B,3) 8 radius(B)
//  9 cls_emb(NB,51) f32  10 rel_emb(NB,2601) f32
// ---------------------------------------------------------------------------
extern "C" void kernel_launch(void* const* d_in, const int* in_sizes, int n_in,
                              void* d_out, int out_size)
{
    const int*   nf1    = (const int*)d_in[0];
    const int*   nf2    = (const int*)d_in[1];
    const int*   nf3    = (const int*)d_in[2];
    const int*   nf4    = (const int*)d_in[3];
    const int*   top    = (const int*)d_in[4];
    const int*   nf3n   = (const int*)d_in[5];
    const int*   nfc    = (const int*)d_in[7];
    const int*   radius = (const int*)d_in[8];
    const float* cls    = (const float*)d_in[9];
    const float* rel    = (const float*)d_in[10];
    float*       out    = (float*)d_out;

    chain_kernel<<<CHAIN_BLOCKS, 64>>>(nfc, rel);
    bmv_kernel<<<BMV_BLOCKS, BMV_WPB * 32>>>(nf1, nf3, nf4, nf3n, cls, rel);
    small_kernel<<<SMALL_BLOCKS, SMALL_TPB>>>(nf2, top, radius, cls);
    finish_kernel<<<1, 1024>>>(out);
}

// round 3
// speedup vs baseline: 1.4121x; 1.4121x over previous
#include <cuda_runtime.h>

#define NB    50000
#define DIM   51
#define DD    2601
#define BATCH 8192

#define CHAIN_BLOCKS 4096                      // 2 samples per block
#define BMV_BLOCKS   8192                      // 4 warp-samples per block
#define SMALL_BLOCKS 64                        // 128 samples per block
#define MIX_BLOCKS   (CHAIN_BLOCKS + BMV_BLOCKS)   // 12288 (interleaved % 3)
#define TOTAL_BLOCKS (MIX_BLOCKS + SMALL_BLOCKS)   // 12352

__device__ float g_part[TOTAL_BLOCKS];

// ---- packed f32x2 helpers (sm_100+ FFMA2) ---------------------------------
__device__ __forceinline__ unsigned long long pack2(float lo, float hi) {
    unsigned long long r;
    asm("mov.b64 %0, {%1, %2};" : "=l"(r) : "f"(lo), "f"(hi));
    return r;
}
__device__ __forceinline__ void unpack2(unsigned long long v, float &lo, float &hi) {
    asm("mov.b64 {%0, %1}, %2;" : "=f"(lo), "=f"(hi) : "l"(v));
}
__device__ __forceinline__ void ffma2(unsigned long long &d,
                                      unsigned long long a, unsigned long long b) {
    asm("fma.rn.f32x2 %0, %1, %2, %3;" : "=l"(d) : "l"(a), "l"(b), "l"(d));
}

// ===========================================================================
// Fused kernel: block type by blockIdx.
//   g < 12288 : g%3==0 -> chain block (id g/3), else bmv block
//   g >= 12288: small block
// Every block writes exactly one partial to g_part[blockIdx.x].
// ===========================================================================
__global__ void __launch_bounds__(128) fused_kernel(
    const int* __restrict__ nf1,  const int* __restrict__ nf2,
    const int* __restrict__ nf3,  const int* __restrict__ nf4,
    const int* __restrict__ top,  const int* __restrict__ nf3n,
    const int* __restrict__ nfc,  const int* __restrict__ radius,
    const float* __restrict__ cls, const float* __restrict__ rel)
{
    __shared__ __align__(16) float Cs[2][DIM * 52];   // padded C tiles (chain)
    __shared__ float red[4];

    const int g   = blockIdx.x;
    const int tid = threadIdx.x;

    if (g < MIX_BLOCKS && (g % 3) == 0) {
        // ------------------------- CHAIN ----------------------------------
        // 2 samples/block; sub-block of 64 threads per sample; thread j owns
        // output column j. C staged in smem padded to stride 52 (16B aligned),
        // D column packed into 26 b64 regs, inner product via fma.rn.f32x2.
        const int cid = g / 3;
        const int sub = tid >> 6;
        const int j   = tid & 63;
        const int s   = cid * 2 + sub;
        const int i0 = nfc[3 * s], i1 = nfc[3 * s + 1], i2 = nfc[3 * s + 2];

        float* cs = Cs[sub];
        {
            const float* __restrict__ C = rel + (long)i0 * DD;
            for (int t = j; t < DD; t += 64) {
                const int r = t / 51;
                cs[r * 52 + (t - r * 51)] = C[t];
            }
            if (j < DIM) cs[j * 52 + 51] = 0.f;   // zero pad column
        }

        unsigned long long dpk[26];
        if (j < DIM) {
            const float* __restrict__ Dm = rel + (long)i1 * DD;
            #pragma unroll
            for (int p = 0; p < 25; p++)
                dpk[p] = pack2(Dm[(2 * p) * DIM + j], Dm[(2 * p + 1) * DIM + j]);
            dpk[25] = pack2(Dm[50 * DIM + j], 0.f);
        }
        __syncthreads();

        float local = 0.f;
        if (j < DIM) {
            const float* __restrict__ E = rel + (long)i2 * DD;
            #pragma unroll 1
            for (int i = 0; i < DIM; i++) {
                const ulonglong2* __restrict__ crow =
                    (const ulonglong2*)(cs + i * 52);
                unsigned long long q0 = 0ull, q1 = 0ull, q2 = 0ull, q3 = 0ull;
                #pragma unroll
                for (int m = 0; m < 13; m++) {
                    const ulonglong2 v = crow[m];
                    if (m & 1) { ffma2(q2, v.x, dpk[2 * m]); ffma2(q3, v.y, dpk[2 * m + 1]); }
                    else       { ffma2(q0, v.x, dpk[2 * m]); ffma2(q1, v.y, dpk[2 * m + 1]); }
                }
                float l0, h0, l1, h1, l2, h2, l3, h3;
                unpack2(q0, l0, h0); unpack2(q1, l1, h1);
                unpack2(q2, l2, h2); unpack2(q3, l3, h3);
                const float acc = ((l0 + h0) + (l1 + h1)) + ((l2 + h2) + (l3 + h3));
                local += fabsf(E[i * DIM + j] - acc);
            }
        }

        #pragma unroll
        for (int o = 16; o; o >>= 1)
            local += __shfl_xor_sync(0xffffffffu, local, o);
        if ((tid & 31) == 0) red[tid >> 5] = local;
        __syncthreads();
        if (tid == 0)
            g_part[g] = (red[0] + red[1] + red[2] + red[3]) * (1.0f / (float)DD);

    } else if (g < MIX_BLOCKS) {
        // -------------------------- BMV -----------------------------------
        // warp per (mode, sample). y = R(d-c); mode 0 extra: row-50 dots with
        // c and d. Rows unrolled x5 so 10 gathers front-batch per iteration.
        const int bid    = g - g / 3 - 1;                 // 0..8191
        const int wlocal = tid >> 5;
        const int lane   = tid & 31;
        const int w      = bid * 4 + wlocal;              // 0..32767
        const int mode   = w >> 13;
        const int s      = w & (BATCH - 1);

        const int* __restrict__ idx =
            (mode == 0) ? nf1 : (mode == 1) ? nf3 : (mode == 2) ? nf4 : nf3n;
        int ic, ir, id_;
        if (mode == 2) { ir = idx[3 * s]; ic = idx[3 * s + 1]; id_ = idx[3 * s + 2]; }
        else           { ic = idx[3 * s]; ir = idx[3 * s + 1]; id_ = idx[3 * s + 2]; }

        const float* __restrict__ cp = cls + (long)ic  * DIM;
        const float* __restrict__ dp = cls + (long)id_ * DIM;
        const bool hi = (lane < DIM - 32);                // lanes 0..18
        const float c0 = cp[lane];
        const float d0 = dp[lane];
        const float c1 = hi ? cp[lane + 32] : 0.f;
        const float d1 = hi ? dp[lane + 32] : 0.f;
        const float e0 = d0 - c0;
        const float e1 = d1 - c1;

        // regularizers over first 50 dims (element 50 = lane18-hi, excluded)
        float sc = c0 * c0 + ((lane < 18) ? c1 * c1 : 0.f);
        float sd = d0 * d0 + ((lane < 18) ? d1 * d1 : 0.f);
        #pragma unroll
        for (int o = 16; o; o >>= 1) {
            sc += __shfl_xor_sync(0xffffffffu, sc, o);
            sd += __shfl_xor_sync(0xffffffffu, sd, o);
        }
        const float reg_c  = fabsf(sqrtf(sc) - 1.0f);
        const float reg_d  = fabsf(sqrtf(sd) - 1.0f);
        const float c_last = __shfl_sync(0xffffffffu, c1, 18);
        const float d_last = __shfl_sync(0xffffffffu, d1, 18);

        const float* __restrict__ rm = rel + (long)ir * DD;
        float euc2 = 0.f;
        #pragma unroll 1
        for (int ib = 0; ib < 50; ib += 5) {
            float p[5];
            #pragma unroll
            for (int u = 0; u < 5; u++) {
                const float* __restrict__ row = rm + (ib + u) * DIM;
                const float a0 = row[lane];
                const float a1 = hi ? row[lane + 32] : 0.f;
                p[u] = a0 * e0 + a1 * e1;
            }
            #pragma unroll
            for (int o = 16; o; o >>= 1) {
                #pragma unroll
                for (int u = 0; u < 5; u++)
                    p[u] += __shfl_xor_sync(0xffffffffu, p[u], o);
            }
            #pragma unroll
            for (int u = 0; u < 5; u++)
                euc2 = fmaf(p[u], p[u], euc2);
        }
        const float euc = sqrtf(euc2);

        float core;
        if (mode == 0) {
            const float* __restrict__ row = rm + 50 * DIM;
            const float a0 = row[lane];
            const float a1 = hi ? row[lane + 32] : 0.f;
            float pc = a0 * c0 + a1 * c1;
            float pd = a0 * d0 + a1 * d1;
            #pragma unroll
            for (int o = 16; o; o >>= 1) {
                pc += __shfl_xor_sync(0xffffffffu, pc, o);
                pd += __shfl_xor_sync(0xffffffffu, pd, o);
            }
            core = fmaxf(euc + fmaxf(pc, 0.f) - fmaxf(pd, 0.f), 0.f);
        } else {
            const float rc = fmaxf(c_last, 0.f);
            const float rd = fmaxf(d_last, 0.f);
            if (mode == 1)      core = fmaxf(euc + rc - rd, 0.f);
            else if (mode == 2) core = fmaxf(euc - rc - rd, 0.f);
            else                core = rc + rd - euc;            // nf3_neg
        }
        const float loss = core + reg_c + reg_d;

        if (lane == 0) red[wlocal] = loss;
        __syncthreads();
        if (tid == 0)
            g_part[g] = (red[0] + red[1]) + (red[2] + red[3]);

    } else {
        // ------------------------- SMALL (nf2 + top - radius) -------------
        const int s = (g - MIX_BLOCKS) * 128 + tid;
        const float* __restrict__ c = cls + (long)nf2[3 * s]     * DIM;
        const float* __restrict__ d = cls + (long)nf2[3 * s + 1] * DIM;
        const float* __restrict__ e = cls + (long)nf2[3 * s + 2] * DIM;

        float s12 = 0.f, s13 = 0.f, s23 = 0.f, n1 = 0.f, n2 = 0.f, n3 = 0.f;
        #pragma unroll 5
        for (int k = 0; k < DIM - 1; k++) {
            const float x1 = c[k], x2 = d[k], x3 = e[k];
            const float d12 = x2 - x1, d13 = x3 - x1, d23 = x3 - x2;
            s12 = fmaf(d12, d12, s12);
            s13 = fmaf(d13, d13, s13);
            s23 = fmaf(d23, d23, s23);
            n1  = fmaf(x1, x1, n1);
            n2  = fmaf(x2, x2, n2);
            n3  = fmaf(x3, x3, n3);
        }
        const float rc = fmaxf(c[DIM - 1], 0.f);
        const float rd = fmaxf(d[DIM - 1], 0.f);
        const float re = fmaxf(e[DIM - 1], 0.f);
        float v = fmaxf(sqrtf(s12) - (rc + rd), 0.f)
                + fmaxf(sqrtf(s13) - rc, 0.f)
                + fmaxf(sqrtf(s23) - rd, 0.f)
                + fmaxf(fminf(rc, rd) - re, 0.f)
                + fabsf(sqrtf(n1) - 1.f)
                + fabsf(sqrtf(n2) - 1.f)
                + fabsf(sqrtf(n3) - 1.f);

        v += fabsf(fmaxf(cls[(long)top[s] * DIM + (DIM - 1)], 0.f) - 5.0f);
        v -= fminf(0.f, cls[(long)radius[s] * DIM + (DIM - 1)]);

        #pragma unroll
        for (int o = 16; o; o >>= 1)
            v += __shfl_xor_sync(0xffffffffu, v, o);
        if ((tid & 31) == 0) red[tid >> 5] = v;
        __syncthreads();
        if (tid == 0)
            g_part[g] = (red[0] + red[1]) + (red[2] + red[3]);
    }
}

// ---------------------------------------------------------------------------
// Deterministic final reduction -> out[0] = sum / BATCH
// ---------------------------------------------------------------------------
__global__ void __launch_bounds__(1024) finish_kernel(float* __restrict__ out)
{
    float t = 0.f;
    for (int i = threadIdx.x; i < TOTAL_BLOCKS; i += 1024) t += g_part[i];
    #pragma unroll
    for (int o = 16; o; o >>= 1)
        t += __shfl_xor_sync(0xffffffffu, t, o);
    __shared__ float ws[32];
    if ((threadIdx.x & 31) == 0) ws[threadIdx.x >> 5] = t;
    __syncthreads();
    if (threadIdx.x < 32) {
        float v = ws[threadIdx.x];
        #pragma unroll
        for (int o = 16; o; o >>= 1)
            v += __shfl_xor_sync(0xffffffffu, v, o);
        if (threadIdx.x == 0) out[0] = v * (1.0f / (float)BATCH);
    }
}

// ---------------------------------------------------------------------------
// Inputs (metadata order):
//  0 nf1(B,3) 1 nf2(B,3) 2 nf3(B,3) 3 nf4(B,3) 4 top(B) 5 nf3_neg(B,3)
//  6 nf_inclusion(B,2) [unused] 7 nf_chain(B,3) 8 radius(B)
//  9 cls_emb(NB,51) f32  10 rel_emb(NB,2601) f32
// ---------------------------------------------------------------------------
extern "C" void kernel_launch(void* const* d_in, const int* in_sizes, int n_in,
                              void* d_out, int out_size)
{
    const int*   nf1    = (const int*)d_in[0];
    const int*   nf2    = (const int*)d_in[1];
    const int*   nf3    = (const int*)d_in[2];
    const int*   nf4    = (const int*)d_in[3];
    const int*   top    = (const int*)d_in[4];
    const int*   nf3n   = (const int*)d_in[5];
    const int*   nfc    = (const int*)d_in[7];
    const int*   radius = (const int*)d_in[8];
    const float* cls    = (const float*)d_in[9];
    const float* rel    = (const float*)d_in[10];
    float*       out    = (float*)d_out;

    fused_kernel<<<TOTAL_BLOCKS, 128>>>(nf1, nf2, nf3, nf4, top, nf3n,
                                        nfc, radius, cls, rel);
    finish_kernel<<<1, 1024>>>(out);
}